// round 11
// baseline (speedup 1.0000x reference)
// R11: R10 resubmission with the misaligned-LDS.128 hazard fixed:
// all __shared__ arrays accessed via 16B vector casts now carry
// __align__(16) (float arrays are otherwise only 4B-guaranteed; a
// misaligned LDS.128 traps and would kill the container exactly as seen).
// Algorithm identical to R10: N-pair f32x2 accumulators, pre-duplicated
// A smem, 21 issue slots/kk, ~80 regs -> 3 CTAs/SM.
#include <cuda_runtime.h>
#include <math.h>
#include <stdint.h>

#define NN 50000       // nodes
#define KD 512         // input feature dim
#define FO 256         // output classes
#define ER 850000      // edges: 800000 random + 50000 self loops

// -------- scratch (device globals; no allocation allowed) --------
__device__ __align__(16) float g_h[(size_t)NN * FO];   // h = x@W (51.2 MB)
__device__ float g_srow[NN];
__device__ float g_scol[NN];
__device__ int   g_cnt[NN];      // per-row degree
__device__ int   g_off[NN];      // CSR row start
__device__ int   g_cur[NN];      // fill cursor
__device__ int   g_ecol[ER];     // CSR: source node of each edge
__device__ float g_eval[ER];     // CSR: attention coefficient e
#define SCAN_B 196               // scan blocks (196*256 = 50176 >= NN)
__device__ int   g_part[SCAN_B]; // per-block partial sums

// ---- packed f32x2 helpers ----
__device__ __forceinline__ uint64_t pack2(float lo, float hi) {
    uint64_t p;
    asm("mov.b64 %0, {%1, %2};" : "=l"(p) : "f"(lo), "f"(hi));
    return p;
}
__device__ __forceinline__ void unpack2(uint64_t p, float &lo, float &hi) {
    asm("mov.b64 {%0, %1}, %2;" : "=f"(lo), "=f"(hi) : "l"(p));
}
__device__ __forceinline__ void fma2(uint64_t &d, uint64_t a, uint64_t b) {
    asm("fma.rn.f32x2 %0, %1, %2, %0;" : "+l"(d) : "l"(a), "l"(b));
}

// ============ K1: SGEMM h = x @ W, f32x2, N-pair accumulators ============
// CTA 128(M) x 64(N), BK=16, 256 threads, thread tile 8(M) x 4(N).
// acc[i][p] = {C[m][n], C[m][n+1]} for m=ty*8+i, n=tx*4+2p.
// A stored k-major PRE-DUPLICATED: AskD[k][2m]=AskD[k][2m+1]=x[m][k]
// -> a operand needs no broadcast pack; b pairs come native from LDS.128.
#define BM 128
#define BN 64
#define BK 16
#define AD_STRIDE 260   // floats per k-row of AskD (mult of 4 -> LDS.128 aligned)
#define NCHUNK (KD / BK)

__global__ __launch_bounds__(256) void gemm_kernel(const float* __restrict__ x,
                                                   const float* __restrict__ W) {
    __shared__ __align__(16) float AskD[BK * AD_STRIDE];   // 16.6 KB, duplicated k-major
    __shared__ __align__(16) float Bs[BK][BN];             // 4 KB

    const int tid = threadIdx.x;
    const int tx = tid & 15;        // n group (4 cols)
    const int ty = tid >> 4;        // m group (8 rows)
    const int n0 = blockIdx.x * BN;     // N fastest -> x slab shared in L2
    const int m0 = blockIdx.y * BM;

    const int arow = tid >> 1;             // 0..127
    const int ak4  = (tid & 1) * 2;        // float4-group 0..1 / 2..3
    const bool aok = (m0 + arow) < NN;
    const int brow = tid >> 4;             // k (0..15)
    const int bc4  = tid & 15;

    uint64_t acc[8][2];
#pragma unroll
    for (int i = 0; i < 8; i++) { acc[i][0] = pack2(0.f, 0.f); acc[i][1] = pack2(0.f, 0.f); }

    float4 pa[2];      // A prefetch regs (8 floats of one row)
    float4 pb;         // B prefetch reg

    // ---- prologue: load chunk 0 ----
#pragma unroll
    for (int g = 0; g < 2; g++)
        pa[g] = aok ? *(const float4*)&x[(size_t)(m0 + arow) * KD + (ak4 + g) * 4]
                    : make_float4(0.f, 0.f, 0.f, 0.f);
    pb = *(const float4*)&W[(size_t)brow * FO + n0 + bc4 * 4];

    for (int c = 0; c < NCHUNK; c++) {
        // ---- store prefetched chunk to smem (A duplicated) ----
#pragma unroll
        for (int g = 0; g < 2; g++) {
            int kb = (ak4 + g) * 4;
            float v[4] = {pa[g].x, pa[g].y, pa[g].z, pa[g].w};
#pragma unroll
            for (int j = 0; j < 4; j++)
                *(uint64_t*)&AskD[(kb + j) * AD_STRIDE + 2 * arow] = pack2(v[j], v[j]);
        }
        *(float4*)&Bs[brow][bc4 * 4] = pb;
        __syncthreads();

        // ---- issue gmem loads for chunk c+1 ----
        if (c + 1 < NCHUNK) {
            int k0 = (c + 1) * BK;
#pragma unroll
            for (int g = 0; g < 2; g++)
                pa[g] = aok ? *(const float4*)&x[(size_t)(m0 + arow) * KD + k0 + (ak4 + g) * 4]
                            : make_float4(0.f, 0.f, 0.f, 0.f);
            pb = *(const float4*)&W[(size_t)(k0 + brow) * FO + n0 + bc4 * 4];
        }

        // ---- compute 16 kk: 4 LDS.128 (A, broadcast) + 1 LDS.128 (B) + 16 FFMA2 ----
#pragma unroll
        for (int kk = 0; kk < BK; kk++) {
            const float* ap = &AskD[kk * AD_STRIDE + ty * 16];
            ulonglong2 bu = *(const ulonglong2*)&Bs[kk][tx * 4];  // {b0,b1},{b2,b3}
#pragma unroll
            for (int i = 0; i < 4; i++) {
                ulonglong2 au = *(const ulonglong2*)(ap + i * 4); // {a2i,a2i},{a2i+1,a2i+1}
                fma2(acc[2 * i][0],     au.x, bu.x);
                fma2(acc[2 * i][1],     au.x, bu.y);
                fma2(acc[2 * i + 1][0], au.y, bu.x);
                fma2(acc[2 * i + 1][1], au.y, bu.y);
            }
        }
        __syncthreads();
    }

    // ---- epilogue: each thread owns rows m0+ty*8+i, cols n0+tx*4..+3 ----
#pragma unroll
    for (int i = 0; i < 8; i++) {
        int gr = m0 + ty * 8 + i;
        if (gr < NN) {
            float c0, c1, c2, c3;
            unpack2(acc[i][0], c0, c1);
            unpack2(acc[i][1], c2, c3);
            *(float4*)&g_h[(size_t)gr * FO + n0 + tx * 4] = make_float4(c0, c1, c2, c3);
        }
    }
}

// ========= K2: per-node scores + zero degree counters =========
__global__ __launch_bounds__(256) void scores_kernel(const float* __restrict__ a) {
    int n    = blockIdx.x * (blockDim.x >> 5) + (threadIdx.x >> 5);
    int lane = threadIdx.x & 31;
    if (n >= NN) return;
    const float4* h4  = (const float4*)&g_h[(size_t)n * FO];
    const float4* a14 = (const float4*)a;          // a[0:256]
    const float4* a24 = (const float4*)(a + FO);   // a[256:512]
    float s1 = 0.f, s2 = 0.f;
#pragma unroll
    for (int it = 0; it < 2; it++) {
        int idx = lane + it * 32;
        float4 hv = h4[idx];
        float4 va = a14[idx];
        float4 vb = a24[idx];
        s1 += hv.x * va.x + hv.y * va.y + hv.z * va.z + hv.w * va.w;
        s2 += hv.x * vb.x + hv.y * vb.y + hv.z * vb.z + hv.w * vb.w;
    }
#pragma unroll
    for (int off = 16; off; off >>= 1) {
        s1 += __shfl_xor_sync(0xFFFFFFFFu, s1, off);
        s2 += __shfl_xor_sync(0xFFFFFFFFu, s2, off);
    }
    if (lane == 0) {
        g_srow[n] = s1;
        g_scol[n] = s2;
        g_cnt[n]  = 0;
    }
}

// ============ K3: degree histogram ============
__global__ __launch_bounds__(256) void hist_kernel(const int* __restrict__ row) {
    int i = blockIdx.x * blockDim.x + threadIdx.x;
    if (i >= ER) return;
    atomicAdd(&g_cnt[row[i]], 1);
}

// ============ K4a/b/c: 3-pass parallel exclusive scan over g_cnt ============
__global__ __launch_bounds__(256) void scan_reduce() {
    __shared__ __align__(16) int sh[256];
    int t = threadIdx.x;
    int idx = blockIdx.x * 256 + t;
    int v = (idx < NN) ? g_cnt[idx] : 0;
    sh[t] = v;
    __syncthreads();
#pragma unroll
    for (int s = 128; s; s >>= 1) {
        if (t < s) sh[t] += sh[t + s];
        __syncthreads();
    }
    if (t == 0) g_part[blockIdx.x] = sh[0];
}

__global__ __launch_bounds__(256) void scan_partials() {
    __shared__ __align__(16) int sh[256];
    int t = threadIdx.x;
    sh[t] = (t < SCAN_B) ? g_part[t] : 0;
    __syncthreads();
#pragma unroll
    for (int d = 1; d < 256; d <<= 1) {
        int v = (t >= d) ? sh[t - d] : 0;
        __syncthreads();
        sh[t] += v;
        __syncthreads();
    }
    if (t < SCAN_B) g_part[t] = (t > 0) ? sh[t - 1] : 0;   // exclusive
}

__global__ __launch_bounds__(256) void scan_write() {
    __shared__ __align__(16) int sh[256];
    int t = threadIdx.x;
    int idx = blockIdx.x * 256 + t;
    int v = (idx < NN) ? g_cnt[idx] : 0;
    sh[t] = v;
    __syncthreads();
#pragma unroll
    for (int d = 1; d < 256; d <<= 1) {
        int u = (t >= d) ? sh[t - d] : 0;
        __syncthreads();
        sh[t] += u;
        __syncthreads();
    }
    if (idx < NN) {
        int off = g_part[blockIdx.x] + sh[t] - v;   // exclusive = inclusive - self
        g_off[idx] = off;
        g_cur[idx] = off;
    }
}

// ============ K5: per-edge coefficient + CSR fill ============
__global__ __launch_bounds__(256) void edge_kernel(const int* __restrict__ row,
                                                   const int* __restrict__ col) {
    int i = blockIdx.x * blockDim.x + threadIdx.x;
    if (i >= ER) return;
    int r = row[i], c = col[i];
    float z = g_srow[r] + g_scol[c];
    float l = z > 0.f ? z : 0.2f * z;        // leaky_relu, slope 0.2
    float e = expf(-l);
    int pos = atomicAdd(&g_cur[r], 1);
    g_ecol[pos] = c;
    g_eval[pos] = e;
}

// ==== K6: fused gather-reduce + normalize + ELU + log_softmax ====
__device__ __forceinline__ float wred_max(float v) {
#pragma unroll
    for (int o = 16; o; o >>= 1) v = fmaxf(v, __shfl_xor_sync(0xFFFFFFFFu, v, o));
    return v;
}
__device__ __forceinline__ float wred_sum(float v) {
#pragma unroll
    for (int o = 16; o; o >>= 1) v += __shfl_xor_sync(0xFFFFFFFFu, v, o);
    return v;
}

__global__ __launch_bounds__(256) void gather_final(float* __restrict__ out) {
    int n = blockIdx.x;
    int t = threadIdx.x;
    int lane = t & 31;
    int wid  = t >> 5;
    __shared__ __align__(16) float swred[8];

    int start = g_off[n];
    int deg   = g_cnt[n];          // >= 1 (self loop)

    float a0 = 0.f, a1 = 0.f, rs = 0.f;
    int j = 0;
    for (; j + 4 <= deg; j += 4) {
        int   c0 = g_ecol[start + j];
        int   c1 = g_ecol[start + j + 1];
        int   c2 = g_ecol[start + j + 2];
        int   c3 = g_ecol[start + j + 3];
        float e0 = g_eval[start + j];
        float e1 = g_eval[start + j + 1];
        float e2 = g_eval[start + j + 2];
        float e3 = g_eval[start + j + 3];
        float h0 = g_h[(size_t)c0 * FO + t];
        float h1 = g_h[(size_t)c1 * FO + t];
        float h2 = g_h[(size_t)c2 * FO + t];
        float h3 = g_h[(size_t)c3 * FO + t];
        a0 = fmaf(e0, h0, a0);
        a1 = fmaf(e1, h1, a1);
        a0 = fmaf(e2, h2, a0);
        a1 = fmaf(e3, h3, a1);
        rs += (e0 + e1) + (e2 + e3);
    }
    for (; j < deg; j++) {
        int   c0 = g_ecol[start + j];
        float e0 = g_eval[start + j];
        a0 = fmaf(e0, g_h[(size_t)c0 * FO + t], a0);
        rs += e0;
    }

    float v = (a0 + a1) / rs;
    v = v > 0.f ? v : expm1f(v);             // ELU (alpha=1)

    // block max via shuffles
    float m = wred_max(v);
    if (lane == 0) swred[wid] = m;
    __syncthreads();
    if (wid == 0) {
        float mm = (lane < 8) ? swred[lane] : -1e30f;
        mm = wred_max(mm);
        if (lane == 0) swred[0] = mm;
    }
    __syncthreads();
    float mx = swred[0];
    __syncthreads();

    // block sum of exp
    float ex = expf(v - mx);
    float s = wred_sum(ex);
    if (lane == 0) swred[wid] = s;
    __syncthreads();
    if (wid == 0) {
        float ss = (lane < 8) ? swred[lane] : 0.f;
        ss = wred_sum(ss);
        if (lane == 0) swred[0] = ss;
    }
    __syncthreads();
    float lse = logf(swred[0]) + mx;

    out[(size_t)n * FO + t] = v - lse;
}

// ======================= launch =======================
extern "C" void kernel_launch(void* const* d_in, const int* in_sizes, int n_in,
                              void* d_out, int out_size) {
    const float* x  = (const float*)d_in[0];
    const float* W  = (const float*)d_in[1];
    const float* a  = (const float*)d_in[2];
    const int*   ei = (const int*)d_in[3];
    const int*   row = ei;        // edge_index[0]
    const int*   col = ei + ER;   // edge_index[1]
    float* out = (float*)d_out;

    dim3 g1(FO / BN, (NN + BM - 1) / BM);    // N fastest -> x slab reused in L2
    gemm_kernel  <<<g1, 256>>>(x, W);
    scores_kernel<<<(NN + 7) / 8, 256>>>(a);
    hist_kernel  <<<(ER + 255) / 256, 256>>>(row);
    scan_reduce  <<<SCAN_B, 256>>>();
    scan_partials<<<1, 256>>>();
    scan_write   <<<SCAN_B, 256>>>();
    edge_kernel  <<<(ER + 255) / 256, 256>>>(row, col);
    gather_final <<<NN, 256>>>(out);
}

// round 12
// speedup vs baseline: 1.4240x; 1.4240x over previous
// R12: GEMM reverted to R8's exact double-buffered f32x2 version (best known;
// R9/R10/R11 GEMM variants all lost). New gather_final: 4 nodes/block,
// 64 threads/node, float4 h loads (4x fewer LDG, 16B/lane in flight),
// shuffle+2-warp softmax reductions. All vector-cast smem is __align__(16).
#include <cuda_runtime.h>
#include <math.h>
#include <stdint.h>

#define NN 50000       // nodes
#define KD 512         // input feature dim
#define FO 256         // output classes
#define ER 850000      // edges: 800000 random + 50000 self loops

// -------- scratch (device globals; no allocation allowed) --------
__device__ __align__(16) float g_h[(size_t)NN * FO];   // h = x@W (51.2 MB)
__device__ float g_srow[NN];
__device__ float g_scol[NN];
__device__ int   g_cnt[NN];      // per-row degree
__device__ int   g_off[NN];      // CSR row start
__device__ int   g_cur[NN];      // fill cursor
__device__ int   g_ecol[ER];     // CSR: source node of each edge
__device__ float g_eval[ER];     // CSR: attention coefficient e
#define SCAN_B 196               // scan blocks (196*256 = 50176 >= NN)
__device__ int   g_part[SCAN_B]; // per-block partial sums

// ---- packed f32x2 helpers ----
__device__ __forceinline__ uint64_t pack2(float lo, float hi) {
    uint64_t p;
    asm("mov.b64 %0, {%1, %2};" : "=l"(p) : "f"(lo), "f"(hi));
    return p;
}
__device__ __forceinline__ void unpack2(uint64_t p, float &lo, float &hi) {
    asm("mov.b64 {%0, %1}, %2;" : "=f"(lo), "=f"(hi) : "l"(p));
}
__device__ __forceinline__ void fma2(uint64_t &d, uint64_t a, uint64_t b) {
    asm("fma.rn.f32x2 %0, %1, %2, %0;" : "+l"(d) : "l"(a), "l"(b));
}

// ====== K1: SGEMM h = x @ W via fma.rn.f32x2, double-buffered (R8) ======
#define BM 128
#define BN 64
#define BK 16
#define TM 8
#define TN 4
#define AK_STRIDE 130   // floats per k-row (even -> LDS.64 aligned; %32=2 -> banks spread)
#define NCHUNK (KD / BK)

__global__ __launch_bounds__(256) void gemm_kernel(const float* __restrict__ x,
                                                   const float* __restrict__ W) {
    __shared__ __align__(16) float Ask[2][BK * AK_STRIDE];   // k-major: Ask[buf][k][m]
    __shared__ __align__(16) float Bs[2][BK][BN];

    int tid = threadIdx.x;
    int tx = tid & 15;        // N direction (4 cols each)
    int ty = tid >> 4;        // M direction (8 rows each)
    int n0 = blockIdx.x * BN;     // N fastest -> x slab shared in L2
    int m0 = blockIdx.y * BM;

    const int arow = tid >> 1;             // 0..127 (two threads per row)
    const int ak4  = (tid & 1) * 2;        // k-group 0..1 / 2..3
    const bool aok = (m0 + arow) < NN;
    const int brow = tid >> 4;             // 0..15 (k)
    const int bc4  = tid & 15;

    uint64_t acc[TM / 2][TN];
#pragma unroll
    for (int i = 0; i < TM / 2; i++)
#pragma unroll
        for (int j = 0; j < TN; j++) acc[i][j] = pack2(0.f, 0.f);

    // prologue: load chunk 0 into buffer 0
    {
        const float* srcA = x + (size_t)(m0 + arow) * KD + ak4 * 4;
#pragma unroll
        for (int g = 0; g < 2; g++) {
            float4 v = aok ? *(const float4*)(srcA + g * 4)
                           : make_float4(0.f, 0.f, 0.f, 0.f);
            int kb = (ak4 + g) * 4;
            Ask[0][(kb + 0) * AK_STRIDE + arow] = v.x;
            Ask[0][(kb + 1) * AK_STRIDE + arow] = v.y;
            Ask[0][(kb + 2) * AK_STRIDE + arow] = v.z;
            Ask[0][(kb + 3) * AK_STRIDE + arow] = v.w;
        }
        *(float4*)&Bs[0][brow][bc4 * 4] =
            *(const float4*)&W[(size_t)brow * FO + n0 + bc4 * 4];
    }
    __syncthreads();

    for (int c = 0; c < NCHUNK; c++) {
        int buf = c & 1;
        // ---- prefetch chunk c+1 into the other buffer ----
        if (c + 1 < NCHUNK) {
            int nxt = buf ^ 1;
            int k0 = (c + 1) * BK;
            const float* srcA = x + (size_t)(m0 + arow) * KD + k0 + ak4 * 4;
#pragma unroll
            for (int g = 0; g < 2; g++) {
                float4 v = aok ? *(const float4*)(srcA + g * 4)
                               : make_float4(0.f, 0.f, 0.f, 0.f);
                int kb = (ak4 + g) * 4;
                Ask[nxt][(kb + 0) * AK_STRIDE + arow] = v.x;
                Ask[nxt][(kb + 1) * AK_STRIDE + arow] = v.y;
                Ask[nxt][(kb + 2) * AK_STRIDE + arow] = v.z;
                Ask[nxt][(kb + 3) * AK_STRIDE + arow] = v.w;
            }
            *(float4*)&Bs[nxt][brow][bc4 * 4] =
                *(const float4*)&W[(size_t)(k0 + brow) * FO + n0 + bc4 * 4];
        }
        // ---- compute on current buffer ----
#pragma unroll
        for (int kk = 0; kk < BK; kk++) {
            uint64_t ap[TM / 2];
#pragma unroll
            for (int i = 0; i < TM / 2; i++)
                ap[i] = *(const uint64_t*)&Ask[buf][kk * AK_STRIDE + ty * TM + 2 * i];
            float4 b4 = *(float4*)&Bs[buf][kk][tx * TN];
            uint64_t bd[TN] = { pack2(b4.x, b4.x), pack2(b4.y, b4.y),
                                pack2(b4.z, b4.z), pack2(b4.w, b4.w) };
#pragma unroll
            for (int i = 0; i < TM / 2; i++)
#pragma unroll
                for (int j = 0; j < TN; j++)
                    fma2(acc[i][j], ap[i], bd[j]);
        }
        __syncthreads();
    }

    // ---- epilogue ----
#pragma unroll
    for (int i = 0; i < TM / 2; i++) {
        float lo[TN], hi[TN];
#pragma unroll
        for (int j = 0; j < TN; j++) unpack2(acc[i][j], lo[j], hi[j]);
        int gr0 = m0 + ty * TM + 2 * i;
        if (gr0 < NN)
            *(float4*)&g_h[(size_t)gr0 * FO + n0 + tx * TN] =
                make_float4(lo[0], lo[1], lo[2], lo[3]);
        if (gr0 + 1 < NN)
            *(float4*)&g_h[(size_t)(gr0 + 1) * FO + n0 + tx * TN] =
                make_float4(hi[0], hi[1], hi[2], hi[3]);
    }
}

// ========= K2: per-node scores + zero degree counters =========
__global__ __launch_bounds__(256) void scores_kernel(const float* __restrict__ a) {
    int n    = blockIdx.x * (blockDim.x >> 5) + (threadIdx.x >> 5);
    int lane = threadIdx.x & 31;
    if (n >= NN) return;
    const float4* h4  = (const float4*)&g_h[(size_t)n * FO];
    const float4* a14 = (const float4*)a;          // a[0:256]
    const float4* a24 = (const float4*)(a + FO);   // a[256:512]
    float s1 = 0.f, s2 = 0.f;
#pragma unroll
    for (int it = 0; it < 2; it++) {
        int idx = lane + it * 32;
        float4 hv = h4[idx];
        float4 va = a14[idx];
        float4 vb = a24[idx];
        s1 += hv.x * va.x + hv.y * va.y + hv.z * va.z + hv.w * va.w;
        s2 += hv.x * vb.x + hv.y * vb.y + hv.z * vb.z + hv.w * vb.w;
    }
#pragma unroll
    for (int off = 16; off; off >>= 1) {
        s1 += __shfl_xor_sync(0xFFFFFFFFu, s1, off);
        s2 += __shfl_xor_sync(0xFFFFFFFFu, s2, off);
    }
    if (lane == 0) {
        g_srow[n] = s1;
        g_scol[n] = s2;
        g_cnt[n]  = 0;
    }
}

// ============ K3: degree histogram ============
__global__ __launch_bounds__(256) void hist_kernel(const int* __restrict__ row) {
    int i = blockIdx.x * blockDim.x + threadIdx.x;
    if (i >= ER) return;
    atomicAdd(&g_cnt[row[i]], 1);
}

// ============ K4a/b/c: 3-pass parallel exclusive scan over g_cnt ============
__global__ __launch_bounds__(256) void scan_reduce() {
    __shared__ __align__(16) int sh[256];
    int t = threadIdx.x;
    int idx = blockIdx.x * 256 + t;
    int v = (idx < NN) ? g_cnt[idx] : 0;
    sh[t] = v;
    __syncthreads();
#pragma unroll
    for (int s = 128; s; s >>= 1) {
        if (t < s) sh[t] += sh[t + s];
        __syncthreads();
    }
    if (t == 0) g_part[blockIdx.x] = sh[0];
}

__global__ __launch_bounds__(256) void scan_partials() {
    __shared__ __align__(16) int sh[256];
    int t = threadIdx.x;
    sh[t] = (t < SCAN_B) ? g_part[t] : 0;
    __syncthreads();
#pragma unroll
    for (int d = 1; d < 256; d <<= 1) {
        int v = (t >= d) ? sh[t - d] : 0;
        __syncthreads();
        sh[t] += v;
        __syncthreads();
    }
    if (t < SCAN_B) g_part[t] = (t > 0) ? sh[t - 1] : 0;   // exclusive
}

__global__ __launch_bounds__(256) void scan_write() {
    __shared__ __align__(16) int sh[256];
    int t = threadIdx.x;
    int idx = blockIdx.x * 256 + t;
    int v = (idx < NN) ? g_cnt[idx] : 0;
    sh[t] = v;
    __syncthreads();
#pragma unroll
    for (int d = 1; d < 256; d <<= 1) {
        int u = (t >= d) ? sh[t - d] : 0;
        __syncthreads();
        sh[t] += u;
        __syncthreads();
    }
    if (idx < NN) {
        int off = g_part[blockIdx.x] + sh[t] - v;   // exclusive = inclusive - self
        g_off[idx] = off;
        g_cur[idx] = off;
    }
}

// ============ K5: per-edge coefficient + CSR fill ============
__global__ __launch_bounds__(256) void edge_kernel(const int* __restrict__ row,
                                                   const int* __restrict__ col) {
    int i = blockIdx.x * blockDim.x + threadIdx.x;
    if (i >= ER) return;
    int r = row[i], c = col[i];
    float z = g_srow[r] + g_scol[c];
    float l = z > 0.f ? z : 0.2f * z;        // leaky_relu, slope 0.2
    float e = expf(-l);
    int pos = atomicAdd(&g_cur[r], 1);
    g_ecol[pos] = c;
    g_eval[pos] = e;
}

// ==== K6: gather-reduce + normalize + ELU + log_softmax ====
// 4 nodes per 256-thread block; 64 threads (2 whole warps) per node;
// each thread owns 4 features via float4 loads.
__device__ __forceinline__ float wred_max(float v) {
#pragma unroll
    for (int o = 16; o; o >>= 1) v = fmaxf(v, __shfl_xor_sync(0xFFFFFFFFu, v, o));
    return v;
}
__device__ __forceinline__ float wred_sum(float v) {
#pragma unroll
    for (int o = 16; o; o >>= 1) v += __shfl_xor_sync(0xFFFFFFFFu, v, o);
    return v;
}

__global__ __launch_bounds__(256) void gather_final(float* __restrict__ out) {
    const int t     = threadIdx.x;
    const int ng    = t >> 6;            // node group 0..3 (2 warps each)
    const int s     = t & 63;            // sub-thread within node
    const int lane  = t & 31;
    const int warp  = t >> 5;            // 0..7; node ng owns warps 2ng, 2ng+1
    const int n     = blockIdx.x * 4 + ng;   // NN % 4 == 0

    __shared__ __align__(16) float smax[8];
    __shared__ __align__(16) float ssum[8];

    const int start = g_off[n];
    const int deg   = g_cnt[n];          // >= 1 (self loop)
    const int fbase = s * 4;             // features s*4 .. s*4+3

    float4 acc0 = make_float4(0.f, 0.f, 0.f, 0.f);
    float4 acc1 = make_float4(0.f, 0.f, 0.f, 0.f);
    float rs = 0.f;

    int j = 0;
    for (; j + 4 <= deg; j += 4) {
        int   c0 = g_ecol[start + j];
        int   c1 = g_ecol[start + j + 1];
        int   c2 = g_ecol[start + j + 2];
        int   c3 = g_ecol[start + j + 3];
        float e0 = g_eval[start + j];
        float e1 = g_eval[start + j + 1];
        float e2 = g_eval[start + j + 2];
        float e3 = g_eval[start + j + 3];
        float4 h0 = *(const float4*)&g_h[(size_t)c0 * FO + fbase];
        float4 h1 = *(const float4*)&g_h[(size_t)c1 * FO + fbase];
        float4 h2 = *(const float4*)&g_h[(size_t)c2 * FO + fbase];
        float4 h3 = *(const float4*)&g_h[(size_t)c3 * FO + fbase];
        acc0.x = fmaf(e0, h0.x, acc0.x); acc0.y = fmaf(e0, h0.y, acc0.y);
        acc0.z = fmaf(e0, h0.z, acc0.z); acc0.w = fmaf(e0, h0.w, acc0.w);
        acc1.x = fmaf(e1, h1.x, acc1.x); acc1.y = fmaf(e1, h1.y, acc1.y);
        acc1.z = fmaf(e1, h1.z, acc1.z); acc1.w = fmaf(e1, h1.w, acc1.w);
        acc0.x = fmaf(e2, h2.x, acc0.x); acc0.y = fmaf(e2, h2.y, acc0.y);
        acc0.z = fmaf(e2, h2.z, acc0.z); acc0.w = fmaf(e2, h2.w, acc0.w);
        acc1.x = fmaf(e3, h3.x, acc1.x); acc1.y = fmaf(e3, h3.y, acc1.y);
        acc1.z = fmaf(e3, h3.z, acc1.z); acc1.w = fmaf(e3, h3.w, acc1.w);
        rs += (e0 + e1) + (e2 + e3);
    }
    for (; j < deg; j++) {
        int   c0 = g_ecol[start + j];
        float e0 = g_eval[start + j];
        float4 h0 = *(const float4*)&g_h[(size_t)c0 * FO + fbase];
        acc0.x = fmaf(e0, h0.x, acc0.x); acc0.y = fmaf(e0, h0.y, acc0.y);
        acc0.z = fmaf(e0, h0.z, acc0.z); acc0.w = fmaf(e0, h0.w, acc0.w);
        rs += e0;
    }

    float4 v;
    v.x = (acc0.x + acc1.x) / rs;
    v.y = (acc0.y + acc1.y) / rs;
    v.z = (acc0.z + acc1.z) / rs;
    v.w = (acc0.w + acc1.w) / rs;
    v.x = v.x > 0.f ? v.x : expm1f(v.x);     // ELU (alpha=1)
    v.y = v.y > 0.f ? v.y : expm1f(v.y);
    v.z = v.z > 0.f ? v.z : expm1f(v.z);
    v.w = v.w > 0.f ? v.w : expm1f(v.w);

    // ---- node-local max over 256 features (2 warps) ----
    float m = fmaxf(fmaxf(v.x, v.y), fmaxf(v.z, v.w));
    m = wred_max(m);
    if (lane == 0) smax[warp] = m;
    __syncthreads();
    float mx = fmaxf(smax[2 * ng], smax[2 * ng + 1]);

    // ---- node-local sum of exp ----
    float ex = expf(v.x - mx) + expf(v.y - mx) + expf(v.z - mx) + expf(v.w - mx);
    ex = wred_sum(ex);
    if (lane == 0) ssum[warp] = ex;
    __syncthreads();
    float lse = logf(ssum[2 * ng] + ssum[2 * ng + 1]) + mx;

    *(float4*)&out[(size_t)n * FO + fbase] =
        make_float4(v.x - lse, v.y - lse, v.z - lse, v.w - lse);
}

// ======================= launch =======================
extern "C" void kernel_launch(void* const* d_in, const int* in_sizes, int n_in,
                              void* d_out, int out_size) {
    const float* x  = (const float*)d_in[0];
    const float* W  = (const float*)d_in[1];
    const float* a  = (const float*)d_in[2];
    const int*   ei = (const int*)d_in[3];
    const int*   row = ei;        // edge_index[0]
    const int*   col = ei + ER;   // edge_index[1]
    float* out = (float*)d_out;

    dim3 g1(FO / BN, (NN + BM - 1) / BM);    // N fastest -> x slab reused in L2
    gemm_kernel  <<<g1, 256>>>(x, W);
    scores_kernel<<<(NN + 7) / 8, 256>>>(a);
    hist_kernel  <<<(ER + 255) / 256, 256>>>(row);
    scan_reduce  <<<SCAN_B, 256>>>();
    scan_partials<<<1, 256>>>();
    scan_write   <<<SCAN_B, 256>>>();
    edge_kernel  <<<(ER + 255) / 256, 256>>>(row, col);
    gather_final <<<NN / 4, 256>>>(out);
}

// round 14
// speedup vs baseline: 1.4444x; 1.0143x over previous
// R14: bisection round. GEMM inner loop = R12's exact proven version
// (B-dup swizzle from R13 removed — one of R13's two changes killed the
// container; this isolates which). Kept: fused scores epilogue + init kernel.
// Everything else identical to R12 (416us best-known).
#include <cuda_runtime.h>
#include <math.h>
#include <stdint.h>

#define NN 50000       // nodes
#define KD 512         // input feature dim
#define FO 256         // output classes
#define ER 850000      // edges: 800000 random + 50000 self loops

// -------- scratch (device globals; no allocation allowed) --------
__device__ __align__(16) float g_h[(size_t)NN * FO];   // h = x@W (51.2 MB)
__device__ float g_srow[NN];
__device__ float g_scol[NN];
__device__ int   g_cnt[NN];      // per-row degree
__device__ int   g_off[NN];      // CSR row start
__device__ int   g_cur[NN];      // fill cursor
__device__ int   g_ecol[ER];     // CSR: source node of each edge
__device__ float g_eval[ER];     // CSR: attention coefficient e
#define SCAN_B 196               // scan blocks (196*256 = 50176 >= NN)
__device__ int   g_part[SCAN_B]; // per-block partial sums

// ---- packed f32x2 helpers ----
__device__ __forceinline__ uint64_t pack2(float lo, float hi) {
    uint64_t p;
    asm("mov.b64 %0, {%1, %2};" : "=l"(p) : "f"(lo), "f"(hi));
    return p;
}
__device__ __forceinline__ void unpack2(uint64_t p, float &lo, float &hi) {
    asm("mov.b64 {%0, %1}, %2;" : "=f"(lo), "=f"(hi) : "l"(p));
}
__device__ __forceinline__ void fma2(uint64_t &d, uint64_t a, uint64_t b) {
    asm("fma.rn.f32x2 %0, %1, %2, %0;" : "+l"(d) : "l"(a), "l"(b));
}

// ============ K0: zero scores + degree counters ============
__global__ __launch_bounds__(256) void init_kernel() {
    int i = blockIdx.x * blockDim.x + threadIdx.x;
    if (i < NN) {
        g_srow[i] = 0.f;
        g_scol[i] = 0.f;
        g_cnt[i]  = 0;
    }
}

// ====== K1: SGEMM h = x @ W (R12 inner loop) + fused scores epilogue ======
#define BM 128
#define BN 64
#define BK 16
#define TM 8
#define TN 4
#define AK_STRIDE 130   // floats per k-row (even -> LDS.64 aligned; %32=2 -> banks spread)
#define NCHUNK (KD / BK)

__global__ __launch_bounds__(256) void gemm_kernel(const float* __restrict__ x,
                                                   const float* __restrict__ W,
                                                   const float* __restrict__ avec) {
    __shared__ __align__(16) float Ask[2][BK * AK_STRIDE];   // k-major: Ask[buf][k][m]
    __shared__ __align__(16) float Bs[2][BK][BN];
    __shared__ __align__(16) float A1s[BN];                  // a[n0 .. n0+63]
    __shared__ __align__(16) float A2s[BN];                  // a[FO+n0 .. FO+n0+63]

    int tid = threadIdx.x;
    int tx = tid & 15;        // N direction (4 cols each)
    int ty = tid >> 4;        // M direction (8 rows each)
    int n0 = blockIdx.x * BN;     // N fastest -> x slab shared in L2
    int m0 = blockIdx.y * BM;

    const int arow = tid >> 1;             // 0..127 (two threads per row)
    const int ak4  = (tid & 1) * 2;        // k-group 0..1 / 2..3
    const bool aok = (m0 + arow) < NN;
    const int brow = tid >> 4;             // 0..15 (k)
    const int bc4  = tid & 15;

    uint64_t acc[TM / 2][TN];
#pragma unroll
    for (int i = 0; i < TM / 2; i++)
#pragma unroll
        for (int j = 0; j < TN; j++) acc[i][j] = pack2(0.f, 0.f);

    // stage attention-vector slices for the fused score epilogue
    if (tid < BN)             A1s[tid]      = avec[n0 + tid];
    else if (tid < 2 * BN)    A2s[tid - BN] = avec[FO + n0 + tid - BN];

    // prologue: load chunk 0 into buffer 0
    {
        const float* srcA = x + (size_t)(m0 + arow) * KD + ak4 * 4;
#pragma unroll
        for (int g = 0; g < 2; g++) {
            float4 v = aok ? *(const float4*)(srcA + g * 4)
                           : make_float4(0.f, 0.f, 0.f, 0.f);
            int kb = (ak4 + g) * 4;
            Ask[0][(kb + 0) * AK_STRIDE + arow] = v.x;
            Ask[0][(kb + 1) * AK_STRIDE + arow] = v.y;
            Ask[0][(kb + 2) * AK_STRIDE + arow] = v.z;
            Ask[0][(kb + 3) * AK_STRIDE + arow] = v.w;
        }
        *(float4*)&Bs[0][brow][bc4 * 4] =
            *(const float4*)&W[(size_t)brow * FO + n0 + bc4 * 4];
    }
    __syncthreads();

    for (int c = 0; c < NCHUNK; c++) {
        int buf = c & 1;
        // ---- prefetch chunk c+1 into the other buffer ----
        if (c + 1 < NCHUNK) {
            int nxt = buf ^ 1;
            int k0 = (c + 1) * BK;
            const float* srcA = x + (size_t)(m0 + arow) * KD + k0 + ak4 * 4;
#pragma unroll
            for (int g = 0; g < 2; g++) {
                float4 v = aok ? *(const float4*)(srcA + g * 4)
                               : make_float4(0.f, 0.f, 0.f, 0.f);
                int kb = (ak4 + g) * 4;
                Ask[nxt][(kb + 0) * AK_STRIDE + arow] = v.x;
                Ask[nxt][(kb + 1) * AK_STRIDE + arow] = v.y;
                Ask[nxt][(kb + 2) * AK_STRIDE + arow] = v.z;
                Ask[nxt][(kb + 3) * AK_STRIDE + arow] = v.w;
            }
            *(float4*)&Bs[nxt][brow][bc4 * 4] =
                *(const float4*)&W[(size_t)(k0 + brow) * FO + n0 + bc4 * 4];
        }
        // ---- compute on current buffer (R12-proven) ----
#pragma unroll
        for (int kk = 0; kk < BK; kk++) {
            uint64_t ap[TM / 2];
#pragma unroll
            for (int i = 0; i < TM / 2; i++)
                ap[i] = *(const uint64_t*)&Ask[buf][kk * AK_STRIDE + ty * TM + 2 * i];
            float4 b4 = *(float4*)&Bs[buf][kk][tx * TN];
            uint64_t bd[TN] = { pack2(b4.x, b4.x), pack2(b4.y, b4.y),
                                pack2(b4.z, b4.z), pack2(b4.w, b4.w) };
#pragma unroll
            for (int i = 0; i < TM / 2; i++)
#pragma unroll
                for (int j = 0; j < TN; j++)
                    fma2(acc[i][j], ap[i], bd[j]);
        }
        __syncthreads();
    }

    // ---- epilogue: write h + fused partial score dots ----
#pragma unroll
    for (int i = 0; i < TM / 2; i++) {
        float lo[TN], hi[TN];
#pragma unroll
        for (int j = 0; j < TN; j++) unpack2(acc[i][j], lo[j], hi[j]);
        int gr0 = m0 + ty * TM + 2 * i;
        if (gr0 < NN)
            *(float4*)&g_h[(size_t)gr0 * FO + n0 + tx * TN] =
                make_float4(lo[0], lo[1], lo[2], lo[3]);
        if (gr0 + 1 < NN)
            *(float4*)&g_h[(size_t)(gr0 + 1) * FO + n0 + tx * TN] =
                make_float4(hi[0], hi[1], hi[2], hi[3]);

        // partial dot of this 64-col slice with a1/a2, reduced over 16 tx lanes
        float sl1 = 0.f, sl2 = 0.f, sh1 = 0.f, sh2 = 0.f;
#pragma unroll
        for (int j = 0; j < TN; j++) {
            float a1 = A1s[tx * TN + j];
            float a2 = A2s[tx * TN + j];
            sl1 = fmaf(lo[j], a1, sl1);
            sl2 = fmaf(lo[j], a2, sl2);
            sh1 = fmaf(hi[j], a1, sh1);
            sh2 = fmaf(hi[j], a2, sh2);
        }
#pragma unroll
        for (int o = 8; o; o >>= 1) {   // xor of bits 0..3 stays in the 16-lane group
            sl1 += __shfl_xor_sync(0xFFFFFFFFu, sl1, o);
            sl2 += __shfl_xor_sync(0xFFFFFFFFu, sl2, o);
            sh1 += __shfl_xor_sync(0xFFFFFFFFu, sh1, o);
            sh2 += __shfl_xor_sync(0xFFFFFFFFu, sh2, o);
        }
        if (tx == 0) {
            if (gr0 < NN) {
                atomicAdd(&g_srow[gr0], sl1);
                atomicAdd(&g_scol[gr0], sl2);
            }
            if (gr0 + 1 < NN) {
                atomicAdd(&g_srow[gr0 + 1], sh1);
                atomicAdd(&g_scol[gr0 + 1], sh2);
            }
        }
    }
}

// ============ K3: degree histogram ============
__global__ __launch_bounds__(256) void hist_kernel(const int* __restrict__ row) {
    int i = blockIdx.x * blockDim.x + threadIdx.x;
    if (i >= ER) return;
    atomicAdd(&g_cnt[row[i]], 1);
}

// ============ K4a/b/c: 3-pass parallel exclusive scan over g_cnt ============
__global__ __launch_bounds__(256) void scan_reduce() {
    __shared__ __align__(16) int sh[256];
    int t = threadIdx.x;
    int idx = blockIdx.x * 256 + t;
    int v = (idx < NN) ? g_cnt[idx] : 0;
    sh[t] = v;
    __syncthreads();
#pragma unroll
    for (int s = 128; s; s >>= 1) {
        if (t < s) sh[t] += sh[t + s];
        __syncthreads();
    }
    if (t == 0) g_part[blockIdx.x] = sh[0];
}

__global__ __launch_bounds__(256) void scan_partials() {
    __shared__ __align__(16) int sh[256];
    int t = threadIdx.x;
    sh[t] = (t < SCAN_B) ? g_part[t] : 0;
    __syncthreads();
#pragma unroll
    for (int d = 1; d < 256; d <<= 1) {
        int v = (t >= d) ? sh[t - d] : 0;
        __syncthreads();
        sh[t] += v;
        __syncthreads();
    }
    if (t < SCAN_B) g_part[t] = (t > 0) ? sh[t - 1] : 0;   // exclusive
}

__global__ __launch_bounds__(256) void scan_write() {
    __shared__ __align__(16) int sh[256];
    int t = threadIdx.x;
    int idx = blockIdx.x * 256 + t;
    int v = (idx < NN) ? g_cnt[idx] : 0;
    sh[t] = v;
    __syncthreads();
#pragma unroll
    for (int d = 1; d < 256; d <<= 1) {
        int u = (t >= d) ? sh[t - d] : 0;
        __syncthreads();
        sh[t] += u;
        __syncthreads();
    }
    if (idx < NN) {
        int off = g_part[blockIdx.x] + sh[t] - v;   // exclusive = inclusive - self
        g_off[idx] = off;
        g_cur[idx] = off;
    }
}

// ============ K5: per-edge coefficient + CSR fill ============
__global__ __launch_bounds__(256) void edge_kernel(const int* __restrict__ row,
                                                   const int* __restrict__ col) {
    int i = blockIdx.x * blockDim.x + threadIdx.x;
    if (i >= ER) return;
    int r = row[i], c = col[i];
    float z = g_srow[r] + g_scol[c];
    float l = z > 0.f ? z : 0.2f * z;        // leaky_relu, slope 0.2
    float e = expf(-l);
    int pos = atomicAdd(&g_cur[r], 1);
    g_ecol[pos] = c;
    g_eval[pos] = e;
}

// ==== K6: gather-reduce + normalize + ELU + log_softmax (R12, proven) ====
__device__ __forceinline__ float wred_max(float v) {
#pragma unroll
    for (int o = 16; o; o >>= 1) v = fmaxf(v, __shfl_xor_sync(0xFFFFFFFFu, v, o));
    return v;
}
__device__ __forceinline__ float wred_sum(float v) {
#pragma unroll
    for (int o = 16; o; o >>= 1) v += __shfl_xor_sync(0xFFFFFFFFu, v, o);
    return v;
}

__global__ __launch_bounds__(256) void gather_final(float* __restrict__ out) {
    const int t     = threadIdx.x;
    const int ng    = t >> 6;            // node group 0..3 (2 warps each)
    const int s     = t & 63;            // sub-thread within node
    const int lane  = t & 31;
    const int warp  = t >> 5;            // node ng owns warps 2ng, 2ng+1
    const int n     = blockIdx.x * 4 + ng;   // NN % 4 == 0

    __shared__ __align__(16) float smax[8];
    __shared__ __align__(16) float ssum[8];

    const int start = g_off[n];
    const int deg   = g_cnt[n];          // >= 1 (self loop)
    const int fbase = s * 4;             // features s*4 .. s*4+3

    float4 acc0 = make_float4(0.f, 0.f, 0.f, 0.f);
    float4 acc1 = make_float4(0.f, 0.f, 0.f, 0.f);
    float rs = 0.f;

    int j = 0;
    for (; j + 4 <= deg; j += 4) {
        int   c0 = g_ecol[start + j];
        int   c1 = g_ecol[start + j + 1];
        int   c2 = g_ecol[start + j + 2];
        int   c3 = g_ecol[start + j + 3];
        float e0 = g_eval[start + j];
        float e1 = g_eval[start + j + 1];
        float e2 = g_eval[start + j + 2];
        float e3 = g_eval[start + j + 3];
        float4 h0 = *(const float4*)&g_h[(size_t)c0 * FO + fbase];
        float4 h1 = *(const float4*)&g_h[(size_t)c1 * FO + fbase];
        float4 h2 = *(const float4*)&g_h[(size_t)c2 * FO + fbase];
        float4 h3 = *(const float4*)&g_h[(size_t)c3 * FO + fbase];
        acc0.x = fmaf(e0, h0.x, acc0.x); acc0.y = fmaf(e0, h0.y, acc0.y);
        acc0.z = fmaf(e0, h0.z, acc0.z); acc0.w = fmaf(e0, h0.w, acc0.w);
        acc1.x = fmaf(e1, h1.x, acc1.x); acc1.y = fmaf(e1, h1.y, acc1.y);
        acc1.z = fmaf(e1, h1.z, acc1.z); acc1.w = fmaf(e1, h1.w, acc1.w);
        acc0.x = fmaf(e2, h2.x, acc0.x); acc0.y = fmaf(e2, h2.y, acc0.y);
        acc0.z = fmaf(e2, h2.z, acc0.z); acc0.w = fmaf(e2, h2.w, acc0.w);
        acc1.x = fmaf(e3, h3.x, acc1.x); acc1.y = fmaf(e3, h3.y, acc1.y);
        acc1.z = fmaf(e3, h3.z, acc1.z); acc1.w = fmaf(e3, h3.w, acc1.w);
        rs += (e0 + e1) + (e2 + e3);
    }
    for (; j < deg; j++) {
        int   c0 = g_ecol[start + j];
        float e0 = g_eval[start + j];
        float4 h0 = *(const float4*)&g_h[(size_t)c0 * FO + fbase];
        acc0.x = fmaf(e0, h0.x, acc0.x); acc0.y = fmaf(e0, h0.y, acc0.y);
        acc0.z = fmaf(e0, h0.z, acc0.z); acc0.w = fmaf(e0, h0.w, acc0.w);
        rs += e0;
    }

    float4 v;
    v.x = (acc0.x + acc1.x) / rs;
    v.y = (acc0.y + acc1.y) / rs;
    v.z = (acc0.z + acc1.z) / rs;
    v.w = (acc0.w + acc1.w) / rs;
    v.x = v.x > 0.f ? v.x : expm1f(v.x);     // ELU (alpha=1)
    v.y = v.y > 0.f ? v.y : expm1f(v.y);
    v.z = v.z > 0.f ? v.z : expm1f(v.z);
    v.w = v.w > 0.f ? v.w : expm1f(v.w);

    // node-local max over 256 features (2 warps)
    float m = fmaxf(fmaxf(v.x, v.y), fmaxf(v.z, v.w));
    m = wred_max(m);
    if (lane == 0) smax[warp] = m;
    __syncthreads();
    float mx = fmaxf(smax[2 * ng], smax[2 * ng + 1]);

    // node-local sum of exp
    float ex = expf(v.x - mx) + expf(v.y - mx) + expf(v.z - mx) + expf(v.w - mx);
    ex = wred_sum(ex);
    if (lane == 0) ssum[warp] = ex;
    __syncthreads();
    float lse = logf(ssum[2 * ng] + ssum[2 * ng + 1]) + mx;

    *(float4*)&out[(size_t)n * FO + fbase] =
        make_float4(v.x - lse, v.y - lse, v.z - lse, v.w - lse);
}

// ======================= launch =======================
extern "C" void kernel_launch(void* const* d_in, const int* in_sizes, int n_in,
                              void* d_out, int out_size) {
    const float* x  = (const float*)d_in[0];
    const float* W  = (const float*)d_in[1];
    const float* a  = (const float*)d_in[2];
    const int*   ei = (const int*)d_in[3];
    const int*   row = ei;        // edge_index[0]
    const int*   col = ei + ER;   // edge_index[1]
    float* out = (float*)d_out;

    dim3 g1(FO / BN, (NN + BM - 1) / BM);    // N fastest -> x slab reused in L2
    init_kernel  <<<(NN + 255) / 256, 256>>>();
    gemm_kernel  <<<g1, 256>>>(x, W, a);
    hist_kernel  <<<(ER + 255) / 256, 256>>>(row);
    scan_reduce  <<<SCAN_B, 256>>>();
    scan_partials<<<1, 256>>>();
    scan_write   <<<SCAN_B, 256>>>();
    edge_kernel  <<<(ER + 255) / 256, 256>>>(row, col);
    gather_final <<<NN / 4, 256>>>(out);
}

// round 15
// speedup vs baseline: 1.4753x; 1.0214x over previous
// R15: kernels identical to R14 (410us, passing). Launcher now overlaps the
// GEMM-independent chain (hist -> 3-pass scan) on a second stream via the
// capturable fork/join event pattern; edge_kernel joins both chains.
#include <cuda_runtime.h>
#include <math.h>
#include <stdint.h>

#define NN 50000       // nodes
#define KD 512         // input feature dim
#define FO 256         // output classes
#define ER 850000      // edges: 800000 random + 50000 self loops

// -------- scratch (device globals; no allocation allowed) --------
__device__ __align__(16) float g_h[(size_t)NN * FO];   // h = x@W (51.2 MB)
__device__ float g_srow[NN];
__device__ float g_scol[NN];
__device__ int   g_cnt[NN];      // per-row degree
__device__ int   g_off[NN];      // CSR row start
__device__ int   g_cur[NN];      // fill cursor
__device__ int   g_ecol[ER];     // CSR: source node of each edge
__device__ float g_eval[ER];     // CSR: attention coefficient e
#define SCAN_B 196               // scan blocks (196*256 = 50176 >= NN)
__device__ int   g_part[SCAN_B]; // per-block partial sums

// ---- packed f32x2 helpers ----
__device__ __forceinline__ uint64_t pack2(float lo, float hi) {
    uint64_t p;
    asm("mov.b64 %0, {%1, %2};" : "=l"(p) : "f"(lo), "f"(hi));
    return p;
}
__device__ __forceinline__ void unpack2(uint64_t p, float &lo, float &hi) {
    asm("mov.b64 {%0, %1}, %2;" : "=f"(lo), "=f"(hi) : "l"(p));
}
__device__ __forceinline__ void fma2(uint64_t &d, uint64_t a, uint64_t b) {
    asm("fma.rn.f32x2 %0, %1, %2, %0;" : "+l"(d) : "l"(a), "l"(b));
}

// ============ K0: zero scores + degree counters ============
__global__ __launch_bounds__(256) void init_kernel() {
    int i = blockIdx.x * blockDim.x + threadIdx.x;
    if (i < NN) {
        g_srow[i] = 0.f;
        g_scol[i] = 0.f;
        g_cnt[i]  = 0;
    }
}

// ====== K1: SGEMM h = x @ W (R12 inner loop) + fused scores epilogue ======
#define BM 128
#define BN 64
#define BK 16
#define TM 8
#define TN 4
#define AK_STRIDE 130   // floats per k-row (even -> LDS.64 aligned; %32=2 -> banks spread)
#define NCHUNK (KD / BK)

__global__ __launch_bounds__(256) void gemm_kernel(const float* __restrict__ x,
                                                   const float* __restrict__ W,
                                                   const float* __restrict__ avec) {
    __shared__ __align__(16) float Ask[2][BK * AK_STRIDE];   // k-major: Ask[buf][k][m]
    __shared__ __align__(16) float Bs[2][BK][BN];
    __shared__ __align__(16) float A1s[BN];                  // a[n0 .. n0+63]
    __shared__ __align__(16) float A2s[BN];                  // a[FO+n0 .. FO+n0+63]

    int tid = threadIdx.x;
    int tx = tid & 15;        // N direction (4 cols each)
    int ty = tid >> 4;        // M direction (8 rows each)
    int n0 = blockIdx.x * BN;     // N fastest -> x slab shared in L2
    int m0 = blockIdx.y * BM;

    const int arow = tid >> 1;             // 0..127 (two threads per row)
    const int ak4  = (tid & 1) * 2;        // k-group 0..1 / 2..3
    const bool aok = (m0 + arow) < NN;
    const int brow = tid >> 4;             // 0..15 (k)
    const int bc4  = tid & 15;

    uint64_t acc[TM / 2][TN];
#pragma unroll
    for (int i = 0; i < TM / 2; i++)
#pragma unroll
        for (int j = 0; j < TN; j++) acc[i][j] = pack2(0.f, 0.f);

    // stage attention-vector slices for the fused score epilogue
    if (tid < BN)             A1s[tid]      = avec[n0 + tid];
    else if (tid < 2 * BN)    A2s[tid - BN] = avec[FO + n0 + tid - BN];

    // prologue: load chunk 0 into buffer 0
    {
        const float* srcA = x + (size_t)(m0 + arow) * KD + ak4 * 4;
#pragma unroll
        for (int g = 0; g < 2; g++) {
            float4 v = aok ? *(const float4*)(srcA + g * 4)
                           : make_float4(0.f, 0.f, 0.f, 0.f);
            int kb = (ak4 + g) * 4;
            Ask[0][(kb + 0) * AK_STRIDE + arow] = v.x;
            Ask[0][(kb + 1) * AK_STRIDE + arow] = v.y;
            Ask[0][(kb + 2) * AK_STRIDE + arow] = v.z;
            Ask[0][(kb + 3) * AK_STRIDE + arow] = v.w;
        }
        *(float4*)&Bs[0][brow][bc4 * 4] =
            *(const float4*)&W[(size_t)brow * FO + n0 + bc4 * 4];
    }
    __syncthreads();

    for (int c = 0; c < NCHUNK; c++) {
        int buf = c & 1;
        // ---- prefetch chunk c+1 into the other buffer ----
        if (c + 1 < NCHUNK) {
            int nxt = buf ^ 1;
            int k0 = (c + 1) * BK;
            const float* srcA = x + (size_t)(m0 + arow) * KD + k0 + ak4 * 4;
#pragma unroll
            for (int g = 0; g < 2; g++) {
                float4 v = aok ? *(const float4*)(srcA + g * 4)
                               : make_float4(0.f, 0.f, 0.f, 0.f);
                int kb = (ak4 + g) * 4;
                Ask[nxt][(kb + 0) * AK_STRIDE + arow] = v.x;
                Ask[nxt][(kb + 1) * AK_STRIDE + arow] = v.y;
                Ask[nxt][(kb + 2) * AK_STRIDE + arow] = v.z;
                Ask[nxt][(kb + 3) * AK_STRIDE + arow] = v.w;
            }
            *(float4*)&Bs[nxt][brow][bc4 * 4] =
                *(const float4*)&W[(size_t)(k0 + brow) * FO + n0 + bc4 * 4];
        }
        // ---- compute on current buffer (R12-proven) ----
#pragma unroll
        for (int kk = 0; kk < BK; kk++) {
            uint64_t ap[TM / 2];
#pragma unroll
            for (int i = 0; i < TM / 2; i++)
                ap[i] = *(const uint64_t*)&Ask[buf][kk * AK_STRIDE + ty * TM + 2 * i];
            float4 b4 = *(float4*)&Bs[buf][kk][tx * TN];
            uint64_t bd[TN] = { pack2(b4.x, b4.x), pack2(b4.y, b4.y),
                                pack2(b4.z, b4.z), pack2(b4.w, b4.w) };
#pragma unroll
            for (int i = 0; i < TM / 2; i++)
#pragma unroll
                for (int j = 0; j < TN; j++)
                    fma2(acc[i][j], ap[i], bd[j]);
        }
        __syncthreads();
    }

    // ---- epilogue: write h + fused partial score dots ----
#pragma unroll
    for (int i = 0; i < TM / 2; i++) {
        float lo[TN], hi[TN];
#pragma unroll
        for (int j = 0; j < TN; j++) unpack2(acc[i][j], lo[j], hi[j]);
        int gr0 = m0 + ty * TM + 2 * i;
        if (gr0 < NN)
            *(float4*)&g_h[(size_t)gr0 * FO + n0 + tx * TN] =
                make_float4(lo[0], lo[1], lo[2], lo[3]);
        if (gr0 + 1 < NN)
            *(float4*)&g_h[(size_t)(gr0 + 1) * FO + n0 + tx * TN] =
                make_float4(hi[0], hi[1], hi[2], hi[3]);

        // partial dot of this 64-col slice with a1/a2, reduced over 16 tx lanes
        float sl1 = 0.f, sl2 = 0.f, sh1 = 0.f, sh2 = 0.f;
#pragma unroll
        for (int j = 0; j < TN; j++) {
            float a1 = A1s[tx * TN + j];
            float a2 = A2s[tx * TN + j];
            sl1 = fmaf(lo[j], a1, sl1);
            sl2 = fmaf(lo[j], a2, sl2);
            sh1 = fmaf(hi[j], a1, sh1);
            sh2 = fmaf(hi[j], a2, sh2);
        }
#pragma unroll
        for (int o = 8; o; o >>= 1) {   // xor of bits 0..3 stays in the 16-lane group
            sl1 += __shfl_xor_sync(0xFFFFFFFFu, sl1, o);
            sl2 += __shfl_xor_sync(0xFFFFFFFFu, sl2, o);
            sh1 += __shfl_xor_sync(0xFFFFFFFFu, sh1, o);
            sh2 += __shfl_xor_sync(0xFFFFFFFFu, sh2, o);
        }
        if (tx == 0) {
            if (gr0 < NN) {
                atomicAdd(&g_srow[gr0], sl1);
                atomicAdd(&g_scol[gr0], sl2);
            }
            if (gr0 + 1 < NN) {
                atomicAdd(&g_srow[gr0 + 1], sh1);
                atomicAdd(&g_scol[gr0 + 1], sh2);
            }
        }
    }
}

// ============ K3: degree histogram ============
__global__ __launch_bounds__(256) void hist_kernel(const int* __restrict__ row) {
    int i = blockIdx.x * blockDim.x + threadIdx.x;
    if (i >= ER) return;
    atomicAdd(&g_cnt[row[i]], 1);
}

// ============ K4a/b/c: 3-pass parallel exclusive scan over g_cnt ============
__global__ __launch_bounds__(256) void scan_reduce() {
    __shared__ __align__(16) int sh[256];
    int t = threadIdx.x;
    int idx = blockIdx.x * 256 + t;
    int v = (idx < NN) ? g_cnt[idx] : 0;
    sh[t] = v;
    __syncthreads();
#pragma unroll
    for (int s = 128; s; s >>= 1) {
        if (t < s) sh[t] += sh[t + s];
        __syncthreads();
    }
    if (t == 0) g_part[blockIdx.x] = sh[0];
}

__global__ __launch_bounds__(256) void scan_partials() {
    __shared__ __align__(16) int sh[256];
    int t = threadIdx.x;
    sh[t] = (t < SCAN_B) ? g_part[t] : 0;
    __syncthreads();
#pragma unroll
    for (int d = 1; d < 256; d <<= 1) {
        int v = (t >= d) ? sh[t - d] : 0;
        __syncthreads();
        sh[t] += v;
        __syncthreads();
    }
    if (t < SCAN_B) g_part[t] = (t > 0) ? sh[t - 1] : 0;   // exclusive
}

__global__ __launch_bounds__(256) void scan_write() {
    __shared__ __align__(16) int sh[256];
    int t = threadIdx.x;
    int idx = blockIdx.x * 256 + t;
    int v = (idx < NN) ? g_cnt[idx] : 0;
    sh[t] = v;
    __syncthreads();
#pragma unroll
    for (int d = 1; d < 256; d <<= 1) {
        int u = (t >= d) ? sh[t - d] : 0;
        __syncthreads();
        sh[t] += u;
        __syncthreads();
    }
    if (idx < NN) {
        int off = g_part[blockIdx.x] + sh[t] - v;   // exclusive = inclusive - self
        g_off[idx] = off;
        g_cur[idx] = off;
    }
}

// ============ K5: per-edge coefficient + CSR fill ============
__global__ __launch_bounds__(256) void edge_kernel(const int* __restrict__ row,
                                                   const int* __restrict__ col) {
    int i = blockIdx.x * blockDim.x + threadIdx.x;
    if (i >= ER) return;
    int r = row[i], c = col[i];
    float z = g_srow[r] + g_scol[c];
    float l = z > 0.f ? z : 0.2f * z;        // leaky_relu, slope 0.2
    float e = expf(-l);
    int pos = atomicAdd(&g_cur[r], 1);
    g_ecol[pos] = c;
    g_eval[pos] = e;
}

// ==== K6: gather-reduce + normalize + ELU + log_softmax (R12, proven) ====
__device__ __forceinline__ float wred_max(float v) {
#pragma unroll
    for (int o = 16; o; o >>= 1) v = fmaxf(v, __shfl_xor_sync(0xFFFFFFFFu, v, o));
    return v;
}
__device__ __forceinline__ float wred_sum(float v) {
#pragma unroll
    for (int o = 16; o; o >>= 1) v += __shfl_xor_sync(0xFFFFFFFFu, v, o);
    return v;
}

__global__ __launch_bounds__(256) void gather_final(float* __restrict__ out) {
    const int t     = threadIdx.x;
    const int ng    = t >> 6;            // node group 0..3 (2 warps each)
    const int s     = t & 63;            // sub-thread within node
    const int lane  = t & 31;
    const int warp  = t >> 5;            // node ng owns warps 2ng, 2ng+1
    const int n     = blockIdx.x * 4 + ng;   // NN % 4 == 0

    __shared__ __align__(16) float smax[8];
    __shared__ __align__(16) float ssum[8];

    const int start = g_off[n];
    const int deg   = g_cnt[n];          // >= 1 (self loop)
    const int fbase = s * 4;             // features s*4 .. s*4+3

    float4 acc0 = make_float4(0.f, 0.f, 0.f, 0.f);
    float4 acc1 = make_float4(0.f, 0.f, 0.f, 0.f);
    float rs = 0.f;

    int j = 0;
    for (; j + 4 <= deg; j += 4) {
        int   c0 = g_ecol[start + j];
        int   c1 = g_ecol[start + j + 1];
        int   c2 = g_ecol[start + j + 2];
        int   c3 = g_ecol[start + j + 3];
        float e0 = g_eval[start + j];
        float e1 = g_eval[start + j + 1];
        float e2 = g_eval[start + j + 2];
        float e3 = g_eval[start + j + 3];
        float4 h0 = *(const float4*)&g_h[(size_t)c0 * FO + fbase];
        float4 h1 = *(const float4*)&g_h[(size_t)c1 * FO + fbase];
        float4 h2 = *(const float4*)&g_h[(size_t)c2 * FO + fbase];
        float4 h3 = *(const float4*)&g_h[(size_t)c3 * FO + fbase];
        acc0.x = fmaf(e0, h0.x, acc0.x); acc0.y = fmaf(e0, h0.y, acc0.y);
        acc0.z = fmaf(e0, h0.z, acc0.z); acc0.w = fmaf(e0, h0.w, acc0.w);
        acc1.x = fmaf(e1, h1.x, acc1.x); acc1.y = fmaf(e1, h1.y, acc1.y);
        acc1.z = fmaf(e1, h1.z, acc1.z); acc1.w = fmaf(e1, h1.w, acc1.w);
        acc0.x = fmaf(e2, h2.x, acc0.x); acc0.y = fmaf(e2, h2.y, acc0.y);
        acc0.z = fmaf(e2, h2.z, acc0.z); acc0.w = fmaf(e2, h2.w, acc0.w);
        acc1.x = fmaf(e3, h3.x, acc1.x); acc1.y = fmaf(e3, h3.y, acc1.y);
        acc1.z = fmaf(e3, h3.z, acc1.z); acc1.w = fmaf(e3, h3.w, acc1.w);
        rs += (e0 + e1) + (e2 + e3);
    }
    for (; j < deg; j++) {
        int   c0 = g_ecol[start + j];
        float e0 = g_eval[start + j];
        float4 h0 = *(const float4*)&g_h[(size_t)c0 * FO + fbase];
        acc0.x = fmaf(e0, h0.x, acc0.x); acc0.y = fmaf(e0, h0.y, acc0.y);
        acc0.z = fmaf(e0, h0.z, acc0.z); acc0.w = fmaf(e0, h0.w, acc0.w);
        rs += e0;
    }

    float4 v;
    v.x = (acc0.x + acc1.x) / rs;
    v.y = (acc0.y + acc1.y) / rs;
    v.z = (acc0.z + acc1.z) / rs;
    v.w = (acc0.w + acc1.w) / rs;
    v.x = v.x > 0.f ? v.x : expm1f(v.x);     // ELU (alpha=1)
    v.y = v.y > 0.f ? v.y : expm1f(v.y);
    v.z = v.z > 0.f ? v.z : expm1f(v.z);
    v.w = v.w > 0.f ? v.w : expm1f(v.w);

    // node-local max over 256 features (2 warps)
    float m = fmaxf(fmaxf(v.x, v.y), fmaxf(v.z, v.w));
    m = wred_max(m);
    if (lane == 0) smax[warp] = m;
    __syncthreads();
    float mx = fmaxf(smax[2 * ng], smax[2 * ng + 1]);

    // node-local sum of exp
    float ex = expf(v.x - mx) + expf(v.y - mx) + expf(v.z - mx) + expf(v.w - mx);
    ex = wred_sum(ex);
    if (lane == 0) ssum[warp] = ex;
    __syncthreads();
    float lse = logf(ssum[2 * ng] + ssum[2 * ng + 1]) + mx;

    *(float4*)&out[(size_t)n * FO + fbase] =
        make_float4(v.x - lse, v.y - lse, v.z - lse, v.w - lse);
}

// ======================= launch (fork/join overlap) =======================
extern "C" void kernel_launch(void* const* d_in, const int* in_sizes, int n_in,
                              void* d_out, int out_size) {
    const float* x  = (const float*)d_in[0];
    const float* W  = (const float*)d_in[1];
    const float* a  = (const float*)d_in[2];
    const int*   ei = (const int*)d_in[3];
    const int*   row = ei;        // edge_index[0]
    const int*   col = ei + ER;   // edge_index[1]
    float* out = (float*)d_out;

    // Side stream + events, created per call (host-side objects only; not
    // destroyed here because destruction during an active stream capture
    // would invalidate the capture; the handful of calls bounds the leak).
    cudaStream_t s2;
    cudaStreamCreateWithFlags(&s2, cudaStreamNonBlocking);
    cudaEvent_t evFork, evJoin;
    cudaEventCreateWithFlags(&evFork, cudaEventDisableTiming);
    cudaEventCreateWithFlags(&evJoin, cudaEventDisableTiming);

    dim3 g1(FO / BN, (NN + BM - 1) / BM);    // N fastest -> x slab reused in L2

    // main stream: init (zeroes srow/scol/cnt — needed by BOTH chains)
    init_kernel  <<<(NN + 255) / 256, 256>>>();
    cudaEventRecord(evFork, 0);

    // side stream: hist -> scan (independent of the GEMM)
    cudaStreamWaitEvent(s2, evFork, 0);
    hist_kernel  <<<(ER + 255) / 256, 256, 0, s2>>>(row);
    scan_reduce  <<<SCAN_B, 256, 0, s2>>>();
    scan_partials<<<1, 256, 0, s2>>>();
    scan_write   <<<SCAN_B, 256, 0, s2>>>();
    cudaEventRecord(evJoin, s2);

    // main stream: GEMM runs concurrently with the side chain
    gemm_kernel  <<<g1, 256>>>(x, W, a);

    // join: edge needs scores (GEMM) + CSR offsets (scan)
    cudaStreamWaitEvent(0, evJoin, 0);
    edge_kernel  <<<(ER + 255) / 256, 256>>>(row, col);
    gather_final <<<NN / 4, 256>>>(out);
}

// round 16
// speedup vs baseline: 1.4981x; 1.0155x over previous
// R16: R15 + edge_kernel split: CSR structure fill (no scores needed) moves
// to the side stream (hidden under GEMM); attention coefficients are computed
// inline in gather_final (scol reads are warp-broadcast -> ~free), deleting
// g_eval and removing the 20us edge pass from the critical path.
#include <cuda_runtime.h>
#include <math.h>
#include <stdint.h>

#define NN 50000       // nodes
#define KD 512         // input feature dim
#define FO 256         // output classes
#define ER 850000      // edges: 800000 random + 50000 self loops

// -------- scratch (device globals; no allocation allowed) --------
__device__ __align__(16) float g_h[(size_t)NN * FO];   // h = x@W (51.2 MB)
__device__ float g_srow[NN];
__device__ float g_scol[NN];
__device__ int   g_cnt[NN];      // per-row degree
__device__ int   g_off[NN];      // CSR row start
__device__ int   g_cur[NN];      // fill cursor
__device__ int   g_ecol[ER];     // CSR: source node of each edge
#define SCAN_B 196               // scan blocks (196*256 = 50176 >= NN)
__device__ int   g_part[SCAN_B]; // per-block partial sums

// ---- packed f32x2 helpers ----
__device__ __forceinline__ uint64_t pack2(float lo, float hi) {
    uint64_t p;
    asm("mov.b64 %0, {%1, %2};" : "=l"(p) : "f"(lo), "f"(hi));
    return p;
}
__device__ __forceinline__ void unpack2(uint64_t p, float &lo, float &hi) {
    asm("mov.b64 {%0, %1}, %2;" : "=f"(lo), "=f"(hi) : "l"(p));
}
__device__ __forceinline__ void fma2(uint64_t &d, uint64_t a, uint64_t b) {
    asm("fma.rn.f32x2 %0, %1, %2, %0;" : "+l"(d) : "l"(a), "l"(b));
}

// ============ K0: zero scores + degree counters ============
__global__ __launch_bounds__(256) void init_kernel() {
    int i = blockIdx.x * blockDim.x + threadIdx.x;
    if (i < NN) {
        g_srow[i] = 0.f;
        g_scol[i] = 0.f;
        g_cnt[i]  = 0;
    }
}

// ====== K1: SGEMM h = x @ W (R12 inner loop) + fused scores epilogue ======
#define BM 128
#define BN 64
#define BK 16
#define TM 8
#define TN 4
#define AK_STRIDE 130   // floats per k-row (even -> LDS.64 aligned; %32=2 -> banks spread)
#define NCHUNK (KD / BK)

__global__ __launch_bounds__(256) void gemm_kernel(const float* __restrict__ x,
                                                   const float* __restrict__ W,
                                                   const float* __restrict__ avec) {
    __shared__ __align__(16) float Ask[2][BK * AK_STRIDE];   // k-major: Ask[buf][k][m]
    __shared__ __align__(16) float Bs[2][BK][BN];
    __shared__ __align__(16) float A1s[BN];                  // a[n0 .. n0+63]
    __shared__ __align__(16) float A2s[BN];                  // a[FO+n0 .. FO+n0+63]

    int tid = threadIdx.x;
    int tx = tid & 15;        // N direction (4 cols each)
    int ty = tid >> 4;        // M direction (8 rows each)
    int n0 = blockIdx.x * BN;     // N fastest -> x slab shared in L2
    int m0 = blockIdx.y * BM;

    const int arow = tid >> 1;             // 0..127 (two threads per row)
    const int ak4  = (tid & 1) * 2;        // k-group 0..1 / 2..3
    const bool aok = (m0 + arow) < NN;
    const int brow = tid >> 4;             // 0..15 (k)
    const int bc4  = tid & 15;

    uint64_t acc[TM / 2][TN];
#pragma unroll
    for (int i = 0; i < TM / 2; i++)
#pragma unroll
        for (int j = 0; j < TN; j++) acc[i][j] = pack2(0.f, 0.f);

    // stage attention-vector slices for the fused score epilogue
    if (tid < BN)             A1s[tid]      = avec[n0 + tid];
    else if (tid < 2 * BN)    A2s[tid - BN] = avec[FO + n0 + tid - BN];

    // prologue: load chunk 0 into buffer 0
    {
        const float* srcA = x + (size_t)(m0 + arow) * KD + ak4 * 4;
#pragma unroll
        for (int g = 0; g < 2; g++) {
            float4 v = aok ? *(const float4*)(srcA + g * 4)
                           : make_float4(0.f, 0.f, 0.f, 0.f);
            int kb = (ak4 + g) * 4;
            Ask[0][(kb + 0) * AK_STRIDE + arow] = v.x;
            Ask[0][(kb + 1) * AK_STRIDE + arow] = v.y;
            Ask[0][(kb + 2) * AK_STRIDE + arow] = v.z;
            Ask[0][(kb + 3) * AK_STRIDE + arow] = v.w;
        }
        *(float4*)&Bs[0][brow][bc4 * 4] =
            *(const float4*)&W[(size_t)brow * FO + n0 + bc4 * 4];
    }
    __syncthreads();

    for (int c = 0; c < NCHUNK; c++) {
        int buf = c & 1;
        // ---- prefetch chunk c+1 into the other buffer ----
        if (c + 1 < NCHUNK) {
            int nxt = buf ^ 1;
            int k0 = (c + 1) * BK;
            const float* srcA = x + (size_t)(m0 + arow) * KD + k0 + ak4 * 4;
#pragma unroll
            for (int g = 0; g < 2; g++) {
                float4 v = aok ? *(const float4*)(srcA + g * 4)
                               : make_float4(0.f, 0.f, 0.f, 0.f);
                int kb = (ak4 + g) * 4;
                Ask[nxt][(kb + 0) * AK_STRIDE + arow] = v.x;
                Ask[nxt][(kb + 1) * AK_STRIDE + arow] = v.y;
                Ask[nxt][(kb + 2) * AK_STRIDE + arow] = v.z;
                Ask[nxt][(kb + 3) * AK_STRIDE + arow] = v.w;
            }
            *(float4*)&Bs[nxt][brow][bc4 * 4] =
                *(const float4*)&W[(size_t)(k0 + brow) * FO + n0 + bc4 * 4];
        }
        // ---- compute on current buffer (R12-proven) ----
#pragma unroll
        for (int kk = 0; kk < BK; kk++) {
            uint64_t ap[TM / 2];
#pragma unroll
            for (int i = 0; i < TM / 2; i++)
                ap[i] = *(const uint64_t*)&Ask[buf][kk * AK_STRIDE + ty * TM + 2 * i];
            float4 b4 = *(float4*)&Bs[buf][kk][tx * TN];
            uint64_t bd[TN] = { pack2(b4.x, b4.x), pack2(b4.y, b4.y),
                                pack2(b4.z, b4.z), pack2(b4.w, b4.w) };
#pragma unroll
            for (int i = 0; i < TM / 2; i++)
#pragma unroll
                for (int j = 0; j < TN; j++)
                    fma2(acc[i][j], ap[i], bd[j]);
        }
        __syncthreads();
    }

    // ---- epilogue: write h + fused partial score dots ----
#pragma unroll
    for (int i = 0; i < TM / 2; i++) {
        float lo[TN], hi[TN];
#pragma unroll
        for (int j = 0; j < TN; j++) unpack2(acc[i][j], lo[j], hi[j]);
        int gr0 = m0 + ty * TM + 2 * i;
        if (gr0 < NN)
            *(float4*)&g_h[(size_t)gr0 * FO + n0 + tx * TN] =
                make_float4(lo[0], lo[1], lo[2], lo[3]);
        if (gr0 + 1 < NN)
            *(float4*)&g_h[(size_t)(gr0 + 1) * FO + n0 + tx * TN] =
                make_float4(hi[0], hi[1], hi[2], hi[3]);

        // partial dot of this 64-col slice with a1/a2, reduced over 16 tx lanes
        float sl1 = 0.f, sl2 = 0.f, sh1 = 0.f, sh2 = 0.f;
#pragma unroll
        for (int j = 0; j < TN; j++) {
            float a1 = A1s[tx * TN + j];
            float a2 = A2s[tx * TN + j];
            sl1 = fmaf(lo[j], a1, sl1);
            sl2 = fmaf(lo[j], a2, sl2);
            sh1 = fmaf(hi[j], a1, sh1);
            sh2 = fmaf(hi[j], a2, sh2);
        }
#pragma unroll
        for (int o = 8; o; o >>= 1) {   // xor of bits 0..3 stays in the 16-lane group
            sl1 += __shfl_xor_sync(0xFFFFFFFFu, sl1, o);
            sl2 += __shfl_xor_sync(0xFFFFFFFFu, sl2, o);
            sh1 += __shfl_xor_sync(0xFFFFFFFFu, sh1, o);
            sh2 += __shfl_xor_sync(0xFFFFFFFFu, sh2, o);
        }
        if (tx == 0) {
            if (gr0 < NN) {
                atomicAdd(&g_srow[gr0], sl1);
                atomicAdd(&g_scol[gr0], sl2);
            }
            if (gr0 + 1 < NN) {
                atomicAdd(&g_srow[gr0 + 1], sh1);
                atomicAdd(&g_scol[gr0 + 1], sh2);
            }
        }
    }
}

// ============ K3: degree histogram ============
__global__ __launch_bounds__(256) void hist_kernel(const int* __restrict__ row) {
    int i = blockIdx.x * blockDim.x + threadIdx.x;
    if (i >= ER) return;
    atomicAdd(&g_cnt[row[i]], 1);
}

// ============ K4a/b/c: 3-pass parallel exclusive scan over g_cnt ============
__global__ __launch_bounds__(256) void scan_reduce() {
    __shared__ __align__(16) int sh[256];
    int t = threadIdx.x;
    int idx = blockIdx.x * 256 + t;
    int v = (idx < NN) ? g_cnt[idx] : 0;
    sh[t] = v;
    __syncthreads();
#pragma unroll
    for (int s = 128; s; s >>= 1) {
        if (t < s) sh[t] += sh[t + s];
        __syncthreads();
    }
    if (t == 0) g_part[blockIdx.x] = sh[0];
}

__global__ __launch_bounds__(256) void scan_partials() {
    __shared__ __align__(16) int sh[256];
    int t = threadIdx.x;
    sh[t] = (t < SCAN_B) ? g_part[t] : 0;
    __syncthreads();
#pragma unroll
    for (int d = 1; d < 256; d <<= 1) {
        int v = (t >= d) ? sh[t - d] : 0;
        __syncthreads();
        sh[t] += v;
        __syncthreads();
    }
    if (t < SCAN_B) g_part[t] = (t > 0) ? sh[t - 1] : 0;   // exclusive
}

__global__ __launch_bounds__(256) void scan_write() {
    __shared__ __align__(16) int sh[256];
    int t = threadIdx.x;
    int idx = blockIdx.x * 256 + t;
    int v = (idx < NN) ? g_cnt[idx] : 0;
    sh[t] = v;
    __syncthreads();
#pragma unroll
    for (int d = 1; d < 256; d <<= 1) {
        int u = (t >= d) ? sh[t - d] : 0;
        __syncthreads();
        sh[t] += u;
        __syncthreads();
    }
    if (idx < NN) {
        int off = g_part[blockIdx.x] + sh[t] - v;   // exclusive = inclusive - self
        g_off[idx] = off;
        g_cur[idx] = off;
    }
}

// ============ K5: CSR structure fill (no scores needed -> side stream) ============
__global__ __launch_bounds__(256) void fill_kernel(const int* __restrict__ row,
                                                   const int* __restrict__ col) {
    int i = blockIdx.x * blockDim.x + threadIdx.x;
    if (i >= ER) return;
    int r = row[i];
    int pos = atomicAdd(&g_cur[r], 1);
    g_ecol[pos] = col[i];
}

// ==== K6: gather-reduce with inline coefficients + ELU + log_softmax ====
__device__ __forceinline__ float wred_max(float v) {
#pragma unroll
    for (int o = 16; o; o >>= 1) v = fmaxf(v, __shfl_xor_sync(0xFFFFFFFFu, v, o));
    return v;
}
__device__ __forceinline__ float wred_sum(float v) {
#pragma unroll
    for (int o = 16; o; o >>= 1) v += __shfl_xor_sync(0xFFFFFFFFu, v, o);
    return v;
}
__device__ __forceinline__ float coeff(float srn, float sc) {
    float z = srn + sc;
    float l = z > 0.f ? z : 0.2f * z;        // leaky_relu, slope 0.2
    return expf(-l);
}

__global__ __launch_bounds__(256) void gather_final(float* __restrict__ out) {
    const int t     = threadIdx.x;
    const int ng    = t >> 6;            // node group 0..3 (2 warps each)
    const int s     = t & 63;            // sub-thread within node
    const int lane  = t & 31;
    const int warp  = t >> 5;            // node ng owns warps 2ng, 2ng+1
    const int n     = blockIdx.x * 4 + ng;   // NN % 4 == 0

    __shared__ __align__(16) float smax[8];
    __shared__ __align__(16) float ssum[8];

    const int start = g_off[n];
    const int deg   = g_cnt[n];          // >= 1 (self loop)
    const int fbase = s * 4;             // features s*4 .. s*4+3
    const float srn = g_srow[n];         // uniform per node group

    float4 acc0 = make_float4(0.f, 0.f, 0.f, 0.f);
    float4 acc1 = make_float4(0.f, 0.f, 0.f, 0.f);
    float rs = 0.f;

    int j = 0;
    for (; j + 4 <= deg; j += 4) {
        int   c0 = g_ecol[start + j];        // warp-uniform -> broadcast loads
        int   c1 = g_ecol[start + j + 1];
        int   c2 = g_ecol[start + j + 2];
        int   c3 = g_ecol[start + j + 3];
        float e0 = coeff(srn, g_scol[c0]);   // scol reads warp-uniform too
        float e1 = coeff(srn, g_scol[c1]);
        float e2 = coeff(srn, g_scol[c2]);
        float e3 = coeff(srn, g_scol[c3]);
        float4 h0 = *(const float4*)&g_h[(size_t)c0 * FO + fbase];
        float4 h1 = *(const float4*)&g_h[(size_t)c1 * FO + fbase];
        float4 h2 = *(const float4*)&g_h[(size_t)c2 * FO + fbase];
        float4 h3 = *(const float4*)&g_h[(size_t)c3 * FO + fbase];
        acc0.x = fmaf(e0, h0.x, acc0.x); acc0.y = fmaf(e0, h0.y, acc0.y);
        acc0.z = fmaf(e0, h0.z, acc0.z); acc0.w = fmaf(e0, h0.w, acc0.w);
        acc1.x = fmaf(e1, h1.x, acc1.x); acc1.y = fmaf(e1, h1.y, acc1.y);
        acc1.z = fmaf(e1, h1.z, acc1.z); acc1.w = fmaf(e1, h1.w, acc1.w);
        acc0.x = fmaf(e2, h2.x, acc0.x); acc0.y = fmaf(e2, h2.y, acc0.y);
        acc0.z = fmaf(e2, h2.z, acc0.z); acc0.w = fmaf(e2, h2.w, acc0.w);
        acc1.x = fmaf(e3, h3.x, acc1.x); acc1.y = fmaf(e3, h3.y, acc1.y);
        acc1.z = fmaf(e3, h3.z, acc1.z); acc1.w = fmaf(e3, h3.w, acc1.w);
        rs += (e0 + e1) + (e2 + e3);
    }
    for (; j < deg; j++) {
        int   c0 = g_ecol[start + j];
        float e0 = coeff(srn, g_scol[c0]);
        float4 h0 = *(const float4*)&g_h[(size_t)c0 * FO + fbase];
        acc0.x = fmaf(e0, h0.x, acc0.x); acc0.y = fmaf(e0, h0.y, acc0.y);
        acc0.z = fmaf(e0, h0.z, acc0.z); acc0.w = fmaf(e0, h0.w, acc0.w);
        rs += e0;
    }

    float4 v;
    v.x = (acc0.x + acc1.x) / rs;
    v.y = (acc0.y + acc1.y) / rs;
    v.z = (acc0.z + acc1.z) / rs;
    v.w = (acc0.w + acc1.w) / rs;
    v.x = v.x > 0.f ? v.x : expm1f(v.x);     // ELU (alpha=1)
    v.y = v.y > 0.f ? v.y : expm1f(v.y);
    v.z = v.z > 0.f ? v.z : expm1f(v.z);
    v.w = v.w > 0.f ? v.w : expm1f(v.w);

    // node-local max over 256 features (2 warps)
    float m = fmaxf(fmaxf(v.x, v.y), fmaxf(v.z, v.w));
    m = wred_max(m);
    if (lane == 0) smax[warp] = m;
    __syncthreads();
    float mx = fmaxf(smax[2 * ng], smax[2 * ng + 1]);

    // node-local sum of exp
    float ex = expf(v.x - mx) + expf(v.y - mx) + expf(v.z - mx) + expf(v.w - mx);
    ex = wred_sum(ex);
    if (lane == 0) ssum[warp] = ex;
    __syncthreads();
    float lse = logf(ssum[2 * ng] + ssum[2 * ng + 1]) + mx;

    *(float4*)&out[(size_t)n * FO + fbase] =
        make_float4(v.x - lse, v.y - lse, v.z - lse, v.w - lse);
}

// ======================= launch (fork/join overlap) =======================
extern "C" void kernel_launch(void* const* d_in, const int* in_sizes, int n_in,
                              void* d_out, int out_size) {
    const float* x  = (const float*)d_in[0];
    const float* W  = (const float*)d_in[1];
    const float* a  = (const float*)d_in[2];
    const int*   ei = (const int*)d_in[3];
    const int*   row = ei;        // edge_index[0]
    const int*   col = ei + ER;   // edge_index[1]
    float* out = (float*)d_out;

    // Side stream + events (host objects only; never destroyed mid-capture).
    cudaStream_t s2;
    cudaStreamCreateWithFlags(&s2, cudaStreamNonBlocking);
    cudaEvent_t evFork, evJoin;
    cudaEventCreateWithFlags(&evFork, cudaEventDisableTiming);
    cudaEventCreateWithFlags(&evJoin, cudaEventDisableTiming);

    dim3 g1(FO / BN, (NN + BM - 1) / BM);    // N fastest -> x slab reused in L2

    // main stream: init (zeroes srow/scol/cnt — needed by BOTH chains)
    init_kernel  <<<(NN + 255) / 256, 256>>>();
    cudaEventRecord(evFork, 0);

    // side stream: hist -> scan -> CSR fill (all GEMM-independent)
    cudaStreamWaitEvent(s2, evFork, 0);
    hist_kernel  <<<(ER + 255) / 256, 256, 0, s2>>>(row);
    scan_reduce  <<<SCAN_B, 256, 0, s2>>>();
    scan_partials<<<1, 256, 0, s2>>>();
    scan_write   <<<SCAN_B, 256, 0, s2>>>();
    fill_kernel  <<<(ER + 255) / 256, 256, 0, s2>>>(row, col);
    cudaEventRecord(evJoin, s2);

    // main stream: GEMM runs concurrently with the side chain
    gemm_kernel  <<<g1, 256>>>(x, W, a);

    // join: gather needs scores (GEMM) + CSR (side chain)
    cudaStreamWaitEvent(0, evJoin, 0);
    gather_final <<<NN / 4, 256>>>(out);
}